// round 12
// baseline (speedup 1.0000x reference)
#include <cuda_runtime.h>
#include <cstddef>

// Fixed problem shape: K=64, N=1048576, NS=1024, B=1024
constexpr int   Kdim   = 64;
constexpr long  Nn     = 1048576;
constexpr int   NSs    = 1024;
constexpr int   Bseq   = 1024;
constexpr int   TBLK   = 32;          // staging block (time steps) == renorm period
constexpr int   STRIDE = 36;          // staged row stride (floats), 16B-aligned rows
constexpr float L2E    = 1.4426950408889634f;
constexpr float LN2    = 0.6931471805599453f;

__device__ unsigned gT2[Kdim * 32];    // gT2[k*32+j] = bf16x2(Tp[2j][k], Tp[2j+1][k])
__device__ float    gLpi2[Kdim];       // log_softmax(pi) * log2(e)
__device__ float    gLs[Kdim];         // per-state log2 correction for bf16(T) bias
__device__ float    gPart[Bseq];       // per-sequence log-likelihoods
__device__ unsigned gDone;             // finished-CTA counter

// ---------------------------------------------------------------------------
// helpers
// ---------------------------------------------------------------------------
__device__ __forceinline__ float ex2f(float x) {
    float r; asm("ex2.approx.ftz.f32 %0, %1;" : "=f"(r) : "f"(x)); return r;
}
__device__ __forceinline__ float lg2f(float x) {
    float r; asm("lg2.approx.ftz.f32 %0, %1;" : "=f"(r) : "f"(x)); return r;
}
__device__ __forceinline__ float warp_sum(float v) {
#pragma unroll
    for (int o = 16; o > 0; o >>= 1) v += __shfl_xor_sync(0xffffffffu, v, o);
    return v;
}
__device__ __forceinline__ double warp_sum_d(double v) {
#pragma unroll
    for (int o = 16; o > 0; o >>= 1) v += __shfl_xor_sync(0xffffffffu, v, o);
    return v;
}
__device__ __forceinline__ void hfma2(unsigned& acc, unsigned a, unsigned b) {
    asm("fma.rn.bf16x2 %0, %1, %2, %0;" : "+r"(acc) : "r"(a), "r"(b));
}
__device__ __forceinline__ unsigned hadd2(unsigned a, unsigned b) {
    unsigned r; asm("add.rn.bf16x2 %0, %1, %2;" : "=r"(r) : "r"(a), "r"(b)); return r;
}
__device__ __forceinline__ float blo(unsigned u) { return __uint_as_float(u << 16); }
__device__ __forceinline__ float bhi(unsigned u) { return __uint_as_float(u & 0xffff0000u); }
__device__ __forceinline__ unsigned pack_bf16x2(float lo, float hi) {
    unsigned r; asm("cvt.rn.bf16x2.f32 %0, %1, %2;" : "=r"(r) : "f"(hi), "f"(lo)); return r;
}
__device__ __forceinline__ float bf16r(float x) { return blo(pack_bf16x2(x, 0.f)); }
__device__ __forceinline__ void sts_bf16(unsigned* qbuf, int s, float v) {
    unsigned short h;
    asm("cvt.rn.bf16.f32 %0, %1;" : "=h"(h) : "f"(v));
    unsigned a = (unsigned)__cvta_generic_to_shared((char*)qbuf + s * 2);
    asm volatile("st.shared.b16 [%0], %1;" :: "r"(a), "h"(h));
}
__device__ __forceinline__ void cpasync16(void* dst, const void* src) {
    unsigned d = (unsigned)__cvta_generic_to_shared(dst);
    asm volatile("cp.async.ca.shared.global [%0], [%1], 16;" :: "r"(d), "l"(src));
}
template <int N> __device__ __forceinline__ void wait_group() {
    asm volatile("cp.async.wait_group %0;" :: "n"(N));
}
__device__ __forceinline__ void commit_group() {
    asm volatile("cp.async.commit_group;");
}

// stage one 32-step emission block (64 rows x 32 floats), 64 threads
__device__ __forceinline__ void issue_stage(float* sbuf, const float* gbase, int tid) {
#pragma unroll
    for (int i = 0; i < 8; i++) {
        int m   = (i << 6) + tid;        // 0..511
        int row = m >> 3;
        int c4  = (m & 7) << 2;
        cpasync16(sbuf + row * STRIDE + c4, gbase + (size_t)row * Nn + c4);
    }
    commit_group();
}

// ---------------------------------------------------------------------------
// prep (fused): softmax rows of T -> bf16x2 pack; log_softmax(pi); gLs; gDone
// ---------------------------------------------------------------------------
__global__ void __launch_bounds__(1024) prep_kernel(const float* __restrict__ pi,
                                                    const float* __restrict__ T) {
    __shared__ float sTp[Kdim * Kdim];
    int tid = threadIdx.x, w = tid >> 5, l = tid & 31;
#pragma unroll
    for (int r = w; r < Kdim; r += 32) {
        float a = T[r * Kdim + l], c = T[r * Kdim + l + 32];
        float m = fmaxf(a, c);
#pragma unroll
        for (int o = 16; o > 0; o >>= 1) m = fmaxf(m, __shfl_xor_sync(0xffffffffu, m, o));
        float ea = expf(a - m), ec = expf(c - m);
        float s = warp_sum(ea + ec);
        float inv = 1.0f / s;
        sTp[r * Kdim + l]      = ea * inv;
        sTp[r * Kdim + l + 32] = ec * inv;
    }
    __syncthreads();
    for (int idx = tid; idx < Kdim * 32; idx += 1024) {
        int k = idx >> 5, j = idx & 31;
        gT2[idx] = pack_bf16x2(sTp[(2 * j) * Kdim + k], sTp[(2 * j + 1) * Kdim + k]);
    }
    if (w == 1) {  // log_softmax(pi)
        float pa = pi[l], pb = pi[l + 32];
        float m2 = fmaxf(pa, pb);
#pragma unroll
        for (int o = 16; o > 0; o >>= 1) m2 = fmaxf(m2, __shfl_xor_sync(0xffffffffu, m2, o));
        float sp = warp_sum(expf(pa - m2) + expf(pb - m2));
        float ls = logf(sp);
        gLpi2[l]      = (pa - m2 - ls) * L2E;
        gLpi2[l + 32] = (pb - m2 - ls) * L2E;
    }
    if (tid == 0) gDone = 0u;
    if (w == 0) {  // stationary distribution + bf16(T) bias correction
        float wA = 1.0f / 64.0f, wB = 1.0f / 64.0f;
#pragma unroll 1
        for (int it = 0; it < 24; it++) {
            float nA = 0.f, nB = 0.f;
#pragma unroll 4
            for (int j = 0; j < 32; j++) {
                float wj0 = __shfl_sync(0xffffffffu, wA, j);
                float wj1 = __shfl_sync(0xffffffffu, wB, j);
                nA = fmaf(wj0, sTp[(2 * j) * Kdim + 2 * l],     nA);
                nA = fmaf(wj1, sTp[(2 * j + 1) * Kdim + 2 * l], nA);
                nB = fmaf(wj0, sTp[(2 * j) * Kdim + 2 * l + 1],     nB);
                nB = fmaf(wj1, sTp[(2 * j + 1) * Kdim + 2 * l + 1], nB);
            }
            float S = warp_sum(nA + nB);
            wA = nA / S; wB = nB / S;
        }
        float nA = 0.f, nB = 0.f, dA = 0.f, dB = 0.f;
#pragma unroll 4
        for (int j = 0; j < 32; j++) {
            float wj0 = __shfl_sync(0xffffffffu, wA, j);
            float wj1 = __shfl_sync(0xffffffffu, wB, j);
            float t00 = sTp[(2 * j) * Kdim + 2 * l];
            float t10 = sTp[(2 * j + 1) * Kdim + 2 * l];
            float t01 = sTp[(2 * j) * Kdim + 2 * l + 1];
            float t11 = sTp[(2 * j + 1) * Kdim + 2 * l + 1];
            nA += wj0 * t00 + wj1 * t10;
            nB += wj0 * t01 + wj1 * t11;
            dA += wj0 * bf16r(t00) + wj1 * bf16r(t10);
            dB += wj0 * bf16r(t01) + wj1 * bf16r(t11);
        }
        gLs[2 * l]     = log2f(nA / dA);
        gLs[2 * l + 1] = log2f(nB / dB);
    }
}

// ---------------------------------------------------------------------------
// one forward step, 2-warp CTA: lane owns ONE state s; q exchanged as 64 bf16
// in smem; depth-8 accumulation (4 accs); one __syncthreads per step.
// ---------------------------------------------------------------------------
__device__ __forceinline__ void step(const unsigned* qR, unsigned* qW, int s,
                                     const unsigned* Tc, float e, float gpv,
                                     float& qS) {
    __syncthreads();
    const uint4* qp = (const uint4*)qR;
    unsigned A0 = 0, A1 = 0, A2 = 0, A3 = 0;
#pragma unroll
    for (int i = 0; i < 8; i++) {
        uint4 x = qp[i];
        hfma2(A0, x.x, Tc[4 * i + 0]);
        hfma2(A1, x.y, Tc[4 * i + 1]);
        hfma2(A2, x.z, Tc[4 * i + 2]);
        hfma2(A3, x.w, Tc[4 * i + 3]);
    }
    unsigned a = hadd2(hadd2(A0, A1), hadd2(A2, A3));
    float d = blo(a) + bhi(a);           // fp32 final combine
    float f = ex2f(fmaf(e, L2E, gpv));
    qS = f * d;
    sts_bf16(qW, s, qS);
}

// ---------------------------------------------------------------------------
// forward scan + fused reduction: one 2-warp CTA per sequence (1024 CTAs)
// ---------------------------------------------------------------------------
__global__ void __launch_bounds__(64) fwd_kernel(const float* __restrict__ lp,
                                                 float* __restrict__ out) {
    __shared__ float st[2][Kdim * STRIDE];
    __shared__ __align__(16) unsigned q0[32], q1[32];
    __shared__ float sred[2];
    const int tid = threadIdx.x;
    const int s   = tid;                 // state 0..63
    const int w   = tid >> 5, l = tid & 31;
    const int b   = blockIdx.x;
    const float* base = lp + (size_t)b * NSs;

    issue_stage(st[0], base, tid);
    issue_stage(st[1], base + TBLK, tid);

    unsigned Tc[32];
    {
        const uint4* pt = (const uint4*)(gT2 + s * 32);
#pragma unroll
        for (int i = 0; i < 8; i++) ((uint4*)Tc)[i] = pt[i];
    }
    const float lpi = gLpi2[s];
    const float ls  = gLs[s];

    wait_group<1>();
    __syncthreads();

    // t = 0..3; live q ends in q1 (odd number of swaps after init write to q0)
    float4 e4 = *(const float4*)(st[0] + s * STRIDE);
    float qS = ex2f(fmaf(e4.x, L2E, lpi));
    sts_bf16(q0, s, qS);
    step(q0, q1, s, Tc, e4.y, ls, qS);
    step(q1, q0, s, Tc, e4.z, ls, qS);
    step(q0, q1, s, Tc, e4.w, ls, qS);

    double cacc = 0.0;
    float  gp   = 0.0f;

#pragma unroll 1
    for (int t0 = 4; t0 < NSs; t0 += 4) {
        if ((t0 & (TBLK - 1)) == 0) {
            int k = t0 >> 5;
            if (t0 + TBLK < NSs)
                issue_stage(st[(k + 1) & 1], base + t0 + TBLK, tid);
            float Sp = warp_sum(qS);       // per-warp partial (32 states)
            if (l == 0) sred[w] = Sp;
            if (t0 + TBLK < NSs) wait_group<1>(); else wait_group<0>();
            __syncthreads();               // orders sred + staged data
            float g = lg2f(sred[0] + sred[1]);
            cacc += (double)g;
            gp = -g;
        }
        const float* sb = st[(t0 >> 5) & 1];
        const int tt = t0 & (TBLK - 1);
        float4 e = *(const float4*)(sb + s * STRIDE + tt);

        // groups always start with live q in q1 (4 swaps return it to q1)
        step(q1, q0, s, Tc, e.x, ls + gp, qS);
        step(q0, q1, s, Tc, e.y, ls, qS);
        step(q1, q0, s, Tc, e.z, ls, qS);
        step(q0, q1, s, Tc, e.w, ls, qS);
        gp = 0.0f;
    }

    float Sp = warp_sum(qS);
    if (l == 0) sred[w] = Sp;
    __syncthreads();
    if (tid == 0) gPart[b] = LN2 * (float)(cacc + (double)lg2f(sred[0] + sred[1]));

    // ---- fused deterministic final reduction (last CTA; warp 0 only) ----
    __threadfence();
    if (w == 0) {
        unsigned rank = 0;
        if (l == 0) rank = atomicAdd(&gDone, 1u);
        rank = __shfl_sync(0xffffffffu, rank, 0);
        if (rank == Bseq - 1) {
            __threadfence();
            double v = 0.0;
            for (int i = l; i < Bseq; i += 32) v += (double)gPart[i];  // fixed order
            v = warp_sum_d(v);                                          // fixed tree
            if (l == 0) {
                out[0] = (float)v;
                gDone = 0u;   // reset for next graph replay
            }
        }
    }
}

// ---------------------------------------------------------------------------
extern "C" void kernel_launch(void* const* d_in, const int* in_sizes, int n_in,
                              void* d_out, int out_size) {
    const float* lp = (const float*)d_in[0];  // log_pdf (K, N)
    const float* pi = (const float*)d_in[1];  // pi (K,)
    const float* T  = (const float*)d_in[2];  // T (K, K)
    (void)in_sizes; (void)n_in; (void)out_size;

    prep_kernel<<<1, 1024>>>(pi, T);
    fwd_kernel<<<Bseq, 64>>>(lp, (float*)d_out);
}

// round 13
// speedup vs baseline: 1.0684x; 1.0684x over previous
#include <cuda_runtime.h>
#include <cstddef>

// Fixed problem shape: K=64, N=1048576, NS=1024, B=1024
constexpr int   Kdim   = 64;
constexpr long  Nn     = 1048576;
constexpr int   NSs    = 1024;
constexpr int   Bseq   = 1024;
constexpr int   TBLK   = 32;          // staging block (time steps) == renorm period
constexpr int   STRIDE = 36;          // staged row stride (floats), 16B-aligned rows
constexpr int   WPC    = 8;           // warps (sequences) per CTA
constexpr int   CTAS   = Bseq / WPC;  // 128
constexpr float L2E    = 1.4426950408889634f;
constexpr float LN2    = 0.6931471805599453f;

constexpr int STBYTES = 2 * Kdim * STRIDE * 4;        // 18432 per warp (double buffer)
constexpr int WBYTES  = STBYTES + 256;                // + q0/q1 (128B each)
constexpr int SMEMSZ  = WPC * WBYTES;                 // 149504 B

__device__ unsigned gT2[Kdim * 32];    // gT2[k*32+j] = bf16x2(Tp[2j][k], Tp[2j+1][k])
__device__ float    gLpi2[Kdim];       // log_softmax(pi) * log2(e)
__device__ float    gLs[Kdim];         // per-state log2 correction for bf16(T) bias
__device__ float    gPart[Bseq];       // per-sequence log-likelihoods
__device__ unsigned gDone;             // finished-warp counter

// ---------------------------------------------------------------------------
// helpers
// ---------------------------------------------------------------------------
__device__ __forceinline__ float ex2f(float x) {
    float r; asm("ex2.approx.ftz.f32 %0, %1;" : "=f"(r) : "f"(x)); return r;
}
__device__ __forceinline__ float lg2f(float x) {
    float r; asm("lg2.approx.ftz.f32 %0, %1;" : "=f"(r) : "f"(x)); return r;
}
__device__ __forceinline__ float warp_sum(float v) {
#pragma unroll
    for (int o = 16; o > 0; o >>= 1) v += __shfl_xor_sync(0xffffffffu, v, o);
    return v;
}
__device__ __forceinline__ double warp_sum_d(double v) {
#pragma unroll
    for (int o = 16; o > 0; o >>= 1) v += __shfl_xor_sync(0xffffffffu, v, o);
    return v;
}
__device__ __forceinline__ void hfma2(unsigned& acc, unsigned a, unsigned b) {
    asm("fma.rn.bf16x2 %0, %1, %2, %0;" : "+r"(acc) : "r"(a), "r"(b));
}
__device__ __forceinline__ unsigned hadd2(unsigned a, unsigned b) {
    unsigned r; asm("add.rn.bf16x2 %0, %1, %2;" : "=r"(r) : "r"(a), "r"(b)); return r;
}
__device__ __forceinline__ float blo(unsigned u) { return __uint_as_float(u << 16); }
__device__ __forceinline__ float bhi(unsigned u) { return __uint_as_float(u & 0xffff0000u); }
__device__ __forceinline__ unsigned pack_bf16x2(float lo, float hi) {
    unsigned r; asm("cvt.rn.bf16x2.f32 %0, %1, %2;" : "=r"(r) : "f"(hi), "f"(lo)); return r;
}
__device__ __forceinline__ float bf16r(float x) { return blo(pack_bf16x2(x, 0.f)); }
__device__ __forceinline__ void cpasync16(void* dst, const void* src) {
    unsigned d = (unsigned)__cvta_generic_to_shared(dst);
    asm volatile("cp.async.ca.shared.global [%0], [%1], 16;" :: "r"(d), "l"(src));
}
template <int N> __device__ __forceinline__ void wait_group() {
    asm volatile("cp.async.wait_group %0;" :: "n"(N));
}
__device__ __forceinline__ void commit_group() {
    asm volatile("cp.async.commit_group;");
}

// issue one 32-step emission block (64 rows x 32 floats) into staging buffer
__device__ __forceinline__ void issue_stage(float* sbuf, const float* gbase, int l) {
#pragma unroll
    for (int i = 0; i < 16; i++) {
        int m   = (i << 5) + l;
        int row = m >> 3;
        int c4  = (m & 7) << 2;
        cpasync16(sbuf + row * STRIDE + c4, gbase + (size_t)row * Nn + c4);
    }
    commit_group();
}

// ---------------------------------------------------------------------------
// prep (fused): softmax rows of T -> bf16x2 pack; log_softmax(pi); gLs; gDone
// ---------------------------------------------------------------------------
__global__ void __launch_bounds__(1024) prep_kernel(const float* __restrict__ pi,
                                                    const float* __restrict__ T) {
    __shared__ float sTp[Kdim * Kdim];
    int tid = threadIdx.x, w = tid >> 5, l = tid & 31;
#pragma unroll
    for (int r = w; r < Kdim; r += 32) {
        float a = T[r * Kdim + l], c = T[r * Kdim + l + 32];
        float m = fmaxf(a, c);
#pragma unroll
        for (int o = 16; o > 0; o >>= 1) m = fmaxf(m, __shfl_xor_sync(0xffffffffu, m, o));
        float ea = expf(a - m), ec = expf(c - m);
        float s = warp_sum(ea + ec);
        float inv = 1.0f / s;
        sTp[r * Kdim + l]      = ea * inv;
        sTp[r * Kdim + l + 32] = ec * inv;
    }
    __syncthreads();
    for (int idx = tid; idx < Kdim * 32; idx += 1024) {
        int k = idx >> 5, j = idx & 31;
        gT2[idx] = pack_bf16x2(sTp[(2 * j) * Kdim + k], sTp[(2 * j + 1) * Kdim + k]);
    }
    if (w == 1) {  // log_softmax(pi)
        float pa = pi[l], pb = pi[l + 32];
        float m2 = fmaxf(pa, pb);
#pragma unroll
        for (int o = 16; o > 0; o >>= 1) m2 = fmaxf(m2, __shfl_xor_sync(0xffffffffu, m2, o));
        float sp = warp_sum(expf(pa - m2) + expf(pb - m2));
        float ls = logf(sp);
        gLpi2[l]      = (pa - m2 - ls) * L2E;
        gLpi2[l + 32] = (pb - m2 - ls) * L2E;
    }
    if (tid == 0) gDone = 0u;
    if (w == 0) {  // stationary distribution + bf16(T) bias correction
        float wA = 1.0f / 64.0f, wB = 1.0f / 64.0f;
#pragma unroll 1
        for (int it = 0; it < 24; it++) {
            float nA = 0.f, nB = 0.f;
#pragma unroll 4
            for (int j = 0; j < 32; j++) {
                float wj0 = __shfl_sync(0xffffffffu, wA, j);
                float wj1 = __shfl_sync(0xffffffffu, wB, j);
                nA = fmaf(wj0, sTp[(2 * j) * Kdim + 2 * l],     nA);
                nA = fmaf(wj1, sTp[(2 * j + 1) * Kdim + 2 * l], nA);
                nB = fmaf(wj0, sTp[(2 * j) * Kdim + 2 * l + 1],     nB);
                nB = fmaf(wj1, sTp[(2 * j + 1) * Kdim + 2 * l + 1], nB);
            }
            float S = warp_sum(nA + nB);
            wA = nA / S; wB = nB / S;
        }
        float nA = 0.f, nB = 0.f, dA = 0.f, dB = 0.f;
#pragma unroll 4
        for (int j = 0; j < 32; j++) {
            float wj0 = __shfl_sync(0xffffffffu, wA, j);
            float wj1 = __shfl_sync(0xffffffffu, wB, j);
            float t00 = sTp[(2 * j) * Kdim + 2 * l];
            float t10 = sTp[(2 * j + 1) * Kdim + 2 * l];
            float t01 = sTp[(2 * j) * Kdim + 2 * l + 1];
            float t11 = sTp[(2 * j + 1) * Kdim + 2 * l + 1];
            nA += wj0 * t00 + wj1 * t10;
            nB += wj0 * t01 + wj1 * t11;
            dA += wj0 * bf16r(t00) + wj1 * bf16r(t10);
            dB += wj0 * bf16r(t01) + wj1 * bf16r(t11);
        }
        gLs[2 * l]     = log2f(nA / dA);
        gLs[2 * l + 1] = log2f(nB / dB);
    }
}

// ---------------------------------------------------------------------------
// one forward step: smem ping-pong exchange, depth-8 bf16 accumulation
// lane l owns states (2l, 2l+1) — identical to the R11 hot loop
// ---------------------------------------------------------------------------
__device__ __forceinline__ void step(const unsigned* qR, unsigned* qW, int l,
                                     const unsigned* Ta, const unsigned* Tb,
                                     float eA, float eB, float gpA, float gpB,
                                     float& qA, float& qB) {
    __syncwarp();
    const uint4* qp = (const uint4*)qR;
    unsigned A0 = 0, A1 = 0, A2 = 0, A3 = 0;
    unsigned B0 = 0, B1 = 0, B2 = 0, B3 = 0;
#pragma unroll
    for (int i = 0; i < 8; i++) {
        uint4 w = qp[i];
        hfma2(A0, w.x, Ta[4 * i + 0]);  hfma2(B0, w.x, Tb[4 * i + 0]);
        hfma2(A1, w.y, Ta[4 * i + 1]);  hfma2(B1, w.y, Tb[4 * i + 1]);
        hfma2(A2, w.z, Ta[4 * i + 2]);  hfma2(B2, w.z, Tb[4 * i + 2]);
        hfma2(A3, w.w, Ta[4 * i + 3]);  hfma2(B3, w.w, Tb[4 * i + 3]);
    }
    unsigned a = hadd2(hadd2(A0, A1), hadd2(A2, A3));
    unsigned b = hadd2(hadd2(B0, B1), hadd2(B2, B3));
    float dA = blo(a) + bhi(a);          // fp32 final combine
    float dB = blo(b) + bhi(b);
    float fA = ex2f(fmaf(eA, L2E, gpA));
    float fB = ex2f(fmaf(eB, L2E, gpB));
    qA = fA * dA;
    qB = fB * dB;
    qW[l] = pack_bf16x2(qA, qB);
}

// ---------------------------------------------------------------------------
// forward scan: 128 CTAs x 8 warps, one sequence per warp; warps independent
// (guarantees 2 warps on every SMSP of the 128 active SMs)
// ---------------------------------------------------------------------------
__global__ void __launch_bounds__(WPC * 32, 1) fwd_kernel(const float* __restrict__ lp,
                                                          float* __restrict__ out) {
    extern __shared__ char dsm[];
    const int wid = threadIdx.x >> 5;
    const int l   = threadIdx.x & 31;
    const int b   = blockIdx.x * WPC + wid;
    const float* base = lp + (size_t)b * NSs;

    float*    st0 = (float*)(dsm + wid * WBYTES);
    float*    st1 = st0 + Kdim * STRIDE;
    unsigned* q0  = (unsigned*)(dsm + wid * WBYTES + STBYTES);
    unsigned* q1  = q0 + 32;

    issue_stage(st0, base, l);
    issue_stage(st1, base + TBLK, l);

    unsigned Ta[32], Tb[32];
    {
        const uint4* pa = (const uint4*)(gT2 + (2 * l) * 32);
        const uint4* pb = (const uint4*)(gT2 + (2 * l + 1) * 32);
#pragma unroll
        for (int i = 0; i < 8; i++) { ((uint4*)Ta)[i] = pa[i]; ((uint4*)Tb)[i] = pb[i]; }
    }
    const float lpiA = gLpi2[2 * l], lpiB = gLpi2[2 * l + 1];
    const float lsA  = gLs[2 * l],   lsB  = gLs[2 * l + 1];

    wait_group<1>();
    __syncwarp();

    // t = 0: q = exp2(lp0*log2e + log2_pi); then t = 1..3 (live q ends in q1)
    float4 e4A = *(const float4*)(st0 + (2 * l) * STRIDE);
    float4 e4B = *(const float4*)(st0 + (2 * l + 1) * STRIDE);
    float qA = ex2f(fmaf(e4A.x, L2E, lpiA));
    float qB = ex2f(fmaf(e4B.x, L2E, lpiB));
    q0[l] = pack_bf16x2(qA, qB);
    step(q0, q1, l, Ta, Tb, e4A.y, e4B.y, lsA, lsB, qA, qB);
    step(q1, q0, l, Ta, Tb, e4A.z, e4B.z, lsA, lsB, qA, qB);
    step(q0, q1, l, Ta, Tb, e4A.w, e4B.w, lsA, lsB, qA, qB);

    double cacc = 0.0;
    float  gp   = 0.0f;

#pragma unroll 1
    for (int t0 = 4; t0 < NSs; t0 += 4) {
        if ((t0 & (TBLK - 1)) == 0) {
            int k = t0 >> 5;
            float* dst = (k & 1) ? st1 : st0;     // buffer of block k (just consumed^1)
            // NOTE: block k lives in (k&1); we refill the OTHER buffer ((k+1)&1)
            float* refill = ((k + 1) & 1) ? st1 : st0;
            if (t0 + TBLK < NSs)
                issue_stage(refill, base + t0 + TBLK, l);
            float S = warp_sum(qA + qB);          // renorm every 32 steps
            float g = lg2f(S);
            cacc += (double)g;
            gp = -g;
            if (t0 + TBLK < NSs) wait_group<1>(); else wait_group<0>();
            __syncwarp();
            (void)dst;
        }
        const float* sb = ((t0 >> 5) & 1) ? st1 : st0;
        const int tt = t0 & (TBLK - 1);
        float4 eA = *(const float4*)(sb + (2 * l) * STRIDE + tt);
        float4 eB = *(const float4*)(sb + (2 * l + 1) * STRIDE + tt);

        // groups always start with live q in q1 (4 swaps return it to q1)
        step(q1, q0, l, Ta, Tb, eA.x, eB.x, lsA + gp, lsB + gp, qA, qB);
        step(q0, q1, l, Ta, Tb, eA.y, eB.y, lsA, lsB, qA, qB);
        step(q1, q0, l, Ta, Tb, eA.z, eB.z, lsA, lsB, qA, qB);
        step(q0, q1, l, Ta, Tb, eA.w, eB.w, lsA, lsB, qA, qB);
        gp = 0.0f;
    }

    float S = warp_sum(qA + qB);
    if (l == 0) gPart[b] = LN2 * (float)(cacc + (double)lg2f(S));

    // ---- fused deterministic final reduction (last warp to finish) ----
    __threadfence();
    unsigned rank = 0;
    if (l == 0) rank = atomicAdd(&gDone, 1u);
    rank = __shfl_sync(0xffffffffu, rank, 0);
    if (rank == Bseq - 1) {
        __threadfence();
        double v = 0.0;
        for (int i = l; i < Bseq; i += 32) v += (double)gPart[i];  // fixed order
        v = warp_sum_d(v);                                          // fixed tree
        if (l == 0) {
            out[0] = (float)v;
            gDone = 0u;   // reset for next graph replay (also reset in prep)
        }
    }
}

// ---------------------------------------------------------------------------
extern "C" void kernel_launch(void* const* d_in, const int* in_sizes, int n_in,
                              void* d_out, int out_size) {
    const float* lp = (const float*)d_in[0];  // log_pdf (K, N)
    const float* pi = (const float*)d_in[1];  // pi (K,)
    const float* T  = (const float*)d_in[2];  // T (K, K)
    (void)in_sizes; (void)n_in; (void)out_size;

    cudaFuncSetAttribute(fwd_kernel, cudaFuncAttributeMaxDynamicSharedMemorySize, SMEMSZ);
    prep_kernel<<<1, 1024>>>(pi, T);
    fwd_kernel<<<CTAS, WPC * 32, SMEMSZ>>>(lp, (float*)d_out);
}

// round 14
// speedup vs baseline: 1.0969x; 1.0267x over previous
#include <cuda_runtime.h>
#include <cstddef>

// Fixed problem shape: K=64, N=1048576, NS=1024, B=1024
constexpr int   Kdim   = 64;
constexpr long  Nn     = 1048576;
constexpr int   NSs    = 1024;
constexpr int   Bseq   = 1024;
constexpr int   TBLK   = 32;          // staging block (time steps) == renorm period
constexpr int   STRIDE = 36;          // staged row stride (floats), 16B-aligned rows
constexpr int   WPC    = 8;           // warps (sequences) per CTA
constexpr int   CTAS   = Bseq / WPC;  // 128
constexpr float L2E    = 1.4426950408889634f;
constexpr float LN2    = 0.6931471805599453f;

constexpr int STBYTES = 2 * Kdim * STRIDE * 4;        // 18432 per warp (double buffer)
constexpr int WBYTES  = STBYTES + 256;                // + q0/q1 (128B each)
constexpr int SMEMSZ  = WPC * WBYTES;                 // 149504 B

__device__ unsigned gT2[Kdim * 32];    // gT2[k*32+j] = bf16x2(Tp[2j][k], Tp[2j+1][k])
__device__ float    gLpi2[Kdim];       // log_softmax(pi) * log2(e)
__device__ float    gLs[Kdim];         // per-state log2 correction for bf16(T) bias
__device__ float    gPart[Bseq];       // per-sequence log-likelihoods
__device__ unsigned gDone;             // finished-warp counter

// ---------------------------------------------------------------------------
// helpers
// ---------------------------------------------------------------------------
__device__ __forceinline__ float ex2f(float x) {
    float r; asm("ex2.approx.ftz.f32 %0, %1;" : "=f"(r) : "f"(x)); return r;
}
__device__ __forceinline__ float lg2f(float x) {
    float r; asm("lg2.approx.ftz.f32 %0, %1;" : "=f"(r) : "f"(x)); return r;
}
__device__ __forceinline__ float warp_sum(float v) {
#pragma unroll
    for (int o = 16; o > 0; o >>= 1) v += __shfl_xor_sync(0xffffffffu, v, o);
    return v;
}
__device__ __forceinline__ double warp_sum_d(double v) {
#pragma unroll
    for (int o = 16; o > 0; o >>= 1) v += __shfl_xor_sync(0xffffffffu, v, o);
    return v;
}
__device__ __forceinline__ void hfma2(unsigned& acc, unsigned a, unsigned b) {
    asm("fma.rn.bf16x2 %0, %1, %2, %0;" : "+r"(acc) : "r"(a), "r"(b));
}
__device__ __forceinline__ unsigned hadd2(unsigned a, unsigned b) {
    unsigned r; asm("add.rn.bf16x2 %0, %1, %2;" : "=r"(r) : "r"(a), "r"(b)); return r;
}
__device__ __forceinline__ unsigned hmul2(unsigned a, unsigned b) {
    unsigned r; asm("mul.rn.bf16x2 %0, %1, %2;" : "=r"(r) : "r"(a), "r"(b)); return r;
}
__device__ __forceinline__ unsigned prmt(unsigned a, unsigned b, unsigned sel) {
    unsigned r; asm("prmt.b32 %0, %1, %2, %3;" : "=r"(r) : "r"(a), "r"(b), "r"(sel)); return r;
}
__device__ __forceinline__ float blo(unsigned u) { return __uint_as_float(u << 16); }
__device__ __forceinline__ float bhi(unsigned u) { return __uint_as_float(u & 0xffff0000u); }
__device__ __forceinline__ unsigned pack_bf16x2(float lo, float hi) {
    unsigned r; asm("cvt.rn.bf16x2.f32 %0, %1, %2;" : "=r"(r) : "f"(hi), "f"(lo)); return r;
}
__device__ __forceinline__ float bf16r(float x) { return blo(pack_bf16x2(x, 0.f)); }
__device__ __forceinline__ void cpasync16(void* dst, const void* src) {
    unsigned d = (unsigned)__cvta_generic_to_shared(dst);
    asm volatile("cp.async.ca.shared.global [%0], [%1], 16;" :: "r"(d), "l"(src));
}
template <int N> __device__ __forceinline__ void wait_group() {
    asm volatile("cp.async.wait_group %0;" :: "n"(N));
}
__device__ __forceinline__ void commit_group() {
    asm volatile("cp.async.commit_group;");
}

// issue one 32-step emission block (64 rows x 32 floats) into staging buffer
__device__ __forceinline__ void issue_stage(float* sbuf, const float* gbase, int l) {
#pragma unroll
    for (int i = 0; i < 16; i++) {
        int m   = (i << 5) + l;
        int row = m >> 3;
        int c4  = (m & 7) << 2;
        cpasync16(sbuf + row * STRIDE + c4, gbase + (size_t)row * Nn + c4);
    }
    commit_group();
}

// ---------------------------------------------------------------------------
// prep (fused): softmax rows of T -> bf16x2 pack; log_softmax(pi); gLs; gDone
// ---------------------------------------------------------------------------
__global__ void __launch_bounds__(1024) prep_kernel(const float* __restrict__ pi,
                                                    const float* __restrict__ T) {
    __shared__ float sTp[Kdim * Kdim];
    int tid = threadIdx.x, w = tid >> 5, l = tid & 31;
#pragma unroll
    for (int r = w; r < Kdim; r += 32) {
        float a = T[r * Kdim + l], c = T[r * Kdim + l + 32];
        float m = fmaxf(a, c);
#pragma unroll
        for (int o = 16; o > 0; o >>= 1) m = fmaxf(m, __shfl_xor_sync(0xffffffffu, m, o));
        float ea = expf(a - m), ec = expf(c - m);
        float s = warp_sum(ea + ec);
        float inv = 1.0f / s;
        sTp[r * Kdim + l]      = ea * inv;
        sTp[r * Kdim + l + 32] = ec * inv;
    }
    __syncthreads();
    for (int idx = tid; idx < Kdim * 32; idx += 1024) {
        int k = idx >> 5, j = idx & 31;
        gT2[idx] = pack_bf16x2(sTp[(2 * j) * Kdim + k], sTp[(2 * j + 1) * Kdim + k]);
    }
    if (w == 1) {  // log_softmax(pi)
        float pa = pi[l], pb = pi[l + 32];
        float m2 = fmaxf(pa, pb);
#pragma unroll
        for (int o = 16; o > 0; o >>= 1) m2 = fmaxf(m2, __shfl_xor_sync(0xffffffffu, m2, o));
        float sp = warp_sum(expf(pa - m2) + expf(pb - m2));
        float ls = logf(sp);
        gLpi2[l]      = (pa - m2 - ls) * L2E;
        gLpi2[l + 32] = (pb - m2 - ls) * L2E;
    }
    if (tid == 0) gDone = 0u;
    if (w == 0) {  // stationary distribution + bf16(T) bias correction
        float wA = 1.0f / 64.0f, wB = 1.0f / 64.0f;
#pragma unroll 1
        for (int it = 0; it < 24; it++) {
            float nA = 0.f, nB = 0.f;
#pragma unroll 4
            for (int j = 0; j < 32; j++) {
                float wj0 = __shfl_sync(0xffffffffu, wA, j);
                float wj1 = __shfl_sync(0xffffffffu, wB, j);
                nA = fmaf(wj0, sTp[(2 * j) * Kdim + 2 * l],     nA);
                nA = fmaf(wj1, sTp[(2 * j + 1) * Kdim + 2 * l], nA);
                nB = fmaf(wj0, sTp[(2 * j) * Kdim + 2 * l + 1],     nB);
                nB = fmaf(wj1, sTp[(2 * j + 1) * Kdim + 2 * l + 1], nB);
            }
            float S = warp_sum(nA + nB);
            wA = nA / S; wB = nB / S;
        }
        float nA = 0.f, nB = 0.f, dA = 0.f, dB = 0.f;
#pragma unroll 4
        for (int j = 0; j < 32; j++) {
            float wj0 = __shfl_sync(0xffffffffu, wA, j);
            float wj1 = __shfl_sync(0xffffffffu, wB, j);
            float t00 = sTp[(2 * j) * Kdim + 2 * l];
            float t10 = sTp[(2 * j + 1) * Kdim + 2 * l];
            float t01 = sTp[(2 * j) * Kdim + 2 * l + 1];
            float t11 = sTp[(2 * j + 1) * Kdim + 2 * l + 1];
            nA += wj0 * t00 + wj1 * t10;
            nB += wj0 * t01 + wj1 * t11;
            dA += wj0 * bf16r(t00) + wj1 * bf16r(t10);
            dB += wj0 * bf16r(t01) + wj1 * bf16r(t11);
        }
        gLs[2 * l]     = log2f(nA / dA);
        gLs[2 * l + 1] = log2f(nB / dB);
    }
}

// ---------------------------------------------------------------------------
// one forward step: smem ping-pong exchange, depth-8 bf16 accumulation,
// ALL-bf16 epilogue: PRMT cross-half gather + hadd2 + hmul2 by packed f.
// lane l owns states (2l, 2l+1); qw = packed bf16x2(q_{2l}, q_{2l+1}).
// ---------------------------------------------------------------------------
__device__ __forceinline__ void step(const unsigned* qR, unsigned* qW, int l,
                                     const unsigned* Ta, const unsigned* Tb,
                                     unsigned fpk, unsigned& qw) {
    __syncwarp();
    const uint4* qp = (const uint4*)qR;
    unsigned A0 = 0, A1 = 0, A2 = 0, A3 = 0;
    unsigned B0 = 0, B1 = 0, B2 = 0, B3 = 0;
#pragma unroll
    for (int i = 0; i < 8; i++) {
        uint4 w = qp[i];
        hfma2(A0, w.x, Ta[4 * i + 0]);  hfma2(B0, w.x, Tb[4 * i + 0]);
        hfma2(A1, w.y, Ta[4 * i + 1]);  hfma2(B1, w.y, Tb[4 * i + 1]);
        hfma2(A2, w.z, Ta[4 * i + 2]);  hfma2(B2, w.z, Tb[4 * i + 2]);
        hfma2(A3, w.w, Ta[4 * i + 3]);  hfma2(B3, w.w, Tb[4 * i + 3]);
    }
    unsigned a = hadd2(hadd2(A0, A1), hadd2(A2, A3));   // (aLo, aHi) for state A
    unsigned b = hadd2(hadd2(B0, B1), hadd2(B2, B3));   // (bLo, bHi) for state B
    // cross-half combine, packed: (dA, dB) = (aLo+aHi, bLo+bHi)
    unsigned hi = prmt(a, b, 0x7632u);   // (lo=a.hi, hi=b.hi)
    unsigned lo = prmt(a, b, 0x5410u);   // (lo=a.lo, hi=b.lo)
    unsigned d2 = hadd2(hi, lo);
    qw = hmul2(d2, fpk);                 // q' = f * d, packed bf16x2
    qW[l] = qw;
}

// ---------------------------------------------------------------------------
// forward scan: 128 CTAs x 8 warps, one sequence per warp; warps independent
// ---------------------------------------------------------------------------
__global__ void __launch_bounds__(WPC * 32, 1) fwd_kernel(const float* __restrict__ lp,
                                                          float* __restrict__ out) {
    extern __shared__ char dsm[];
    const int wid = threadIdx.x >> 5;
    const int l   = threadIdx.x & 31;
    const int b   = blockIdx.x * WPC + wid;
    const float* base = lp + (size_t)b * NSs;

    float*    st0 = (float*)(dsm + wid * WBYTES);
    float*    st1 = st0 + Kdim * STRIDE;
    unsigned* q0  = (unsigned*)(dsm + wid * WBYTES + STBYTES);
    unsigned* q1  = q0 + 32;

    issue_stage(st0, base, l);
    issue_stage(st1, base + TBLK, l);

    unsigned Ta[32], Tb[32];
    {
        const uint4* pa = (const uint4*)(gT2 + (2 * l) * 32);
        const uint4* pb = (const uint4*)(gT2 + (2 * l + 1) * 32);
#pragma unroll
        for (int i = 0; i < 8; i++) { ((uint4*)Ta)[i] = pa[i]; ((uint4*)Tb)[i] = pb[i]; }
    }
    const float lpiA = gLpi2[2 * l], lpiB = gLpi2[2 * l + 1];
    const float lsA  = gLs[2 * l],   lsB  = gLs[2 * l + 1];

    wait_group<1>();
    __syncwarp();

    // t = 0: q = exp2(lp0*log2e + log2_pi); then t = 1..3 (live q ends in q1)
    float4 e4A = *(const float4*)(st0 + (2 * l) * STRIDE);
    float4 e4B = *(const float4*)(st0 + (2 * l + 1) * STRIDE);
    unsigned qw = pack_bf16x2(ex2f(fmaf(e4A.x, L2E, lpiA)),
                              ex2f(fmaf(e4B.x, L2E, lpiB)));
    q0[l] = qw;
    {
        unsigned f1 = pack_bf16x2(ex2f(fmaf(e4A.y, L2E, lsA)), ex2f(fmaf(e4B.y, L2E, lsB)));
        unsigned f2 = pack_bf16x2(ex2f(fmaf(e4A.z, L2E, lsA)), ex2f(fmaf(e4B.z, L2E, lsB)));
        unsigned f3 = pack_bf16x2(ex2f(fmaf(e4A.w, L2E, lsA)), ex2f(fmaf(e4B.w, L2E, lsB)));
        step(q0, q1, l, Ta, Tb, f1, qw);
        step(q1, q0, l, Ta, Tb, f2, qw);
        step(q0, q1, l, Ta, Tb, f3, qw);
    }

    double cacc = 0.0;
    float  gp   = 0.0f;

#pragma unroll 1
    for (int t0 = 4; t0 < NSs; t0 += 4) {
        if ((t0 & (TBLK - 1)) == 0) {
            int k = t0 >> 5;
            float* refill = ((k + 1) & 1) ? st1 : st0;
            if (t0 + TBLK < NSs)
                issue_stage(refill, base + t0 + TBLK, l);
            float S = warp_sum(blo(qw) + bhi(qw));        // renorm every 32 steps
            float g = lg2f(S);
            cacc += (double)g;
            gp = -g;
            if (t0 + TBLK < NSs) wait_group<1>(); else wait_group<0>();
            __syncwarp();
        }
        const float* sb = ((t0 >> 5) & 1) ? st1 : st0;
        const int tt = t0 & (TBLK - 1);
        float4 eA = *(const float4*)(sb + (2 * l) * STRIDE + tt);
        float4 eB = *(const float4*)(sb + (2 * l + 1) * STRIDE + tt);

        // off-chain f-factor precompute + pack (bias correction + pending renorm)
        unsigned f0 = pack_bf16x2(ex2f(fmaf(eA.x, L2E, lsA + gp)),
                                  ex2f(fmaf(eB.x, L2E, lsB + gp)));
        unsigned f1 = pack_bf16x2(ex2f(fmaf(eA.y, L2E, lsA)), ex2f(fmaf(eB.y, L2E, lsB)));
        unsigned f2 = pack_bf16x2(ex2f(fmaf(eA.z, L2E, lsA)), ex2f(fmaf(eB.z, L2E, lsB)));
        unsigned f3 = pack_bf16x2(ex2f(fmaf(eA.w, L2E, lsA)), ex2f(fmaf(eB.w, L2E, lsB)));
        gp = 0.0f;

        // groups always start with live q in q1 (4 swaps return it to q1)
        step(q1, q0, l, Ta, Tb, f0, qw);
        step(q0, q1, l, Ta, Tb, f1, qw);
        step(q1, q0, l, Ta, Tb, f2, qw);
        step(q0, q1, l, Ta, Tb, f3, qw);
    }

    float S = warp_sum(blo(qw) + bhi(qw));
    if (l == 0) gPart[b] = LN2 * (float)(cacc + (double)lg2f(S));

    // ---- fused deterministic final reduction (last warp to finish) ----
    __threadfence();
    unsigned rank = 0;
    if (l == 0) rank = atomicAdd(&gDone, 1u);
    rank = __shfl_sync(0xffffffffu, rank, 0);
    if (rank == Bseq - 1) {
        __threadfence();
        double v = 0.0;
        for (int i = l; i < Bseq; i += 32) v += (double)gPart[i];  // fixed order
        v = warp_sum_d(v);                                          // fixed tree
        if (l == 0) {
            out[0] = (float)v;
            gDone = 0u;   // reset for next graph replay (also reset in prep)
        }
    }
}

// ---------------------------------------------------------------------------
extern "C" void kernel_launch(void* const* d_in, const int* in_sizes, int n_in,
                              void* d_out, int out_size) {
    const float* lp = (const float*)d_in[0];  // log_pdf (K, N)
    const float* pi = (const float*)d_in[1];  // pi (K,)
    const float* T  = (const float*)d_in[2];  // T (K, K)
    (void)in_sizes; (void)n_in; (void)out_size;

    cudaFuncSetAttribute(fwd_kernel, cudaFuncAttributeMaxDynamicSharedMemorySize, SMEMSZ);
    prep_kernel<<<1, 1024>>>(pi, T);
    fwd_kernel<<<CTAS, WPC * 32, SMEMSZ>>>(lp, (float*)d_out);
}

// round 15
// speedup vs baseline: 1.1313x; 1.0314x over previous
#include <cuda_runtime.h>
#include <cstddef>

// Fixed problem shape: K=64, N=1048576, NS=1024, B=1024
constexpr int   Kdim   = 64;
constexpr long  Nn     = 1048576;
constexpr int   NSs    = 1024;
constexpr int   Bseq   = 1024;
constexpr int   TBLK   = 32;          // staging block (time steps) == renorm period
constexpr int   STRIDE = 36;          // staged row stride (floats), 16B-aligned rows
constexpr int   WPC    = 8;           // warps (sequences) per CTA
constexpr int   CTAS   = Bseq / WPC;  // 128
constexpr float L2E    = 1.4426950408889634f;
constexpr float LN2    = 0.6931471805599453f;

constexpr int STBYTES = 2 * Kdim * STRIDE * 4;        // 18432 per warp (double buffer)
constexpr int WBYTES  = STBYTES + 256;                // + q0/q1 (128B each)
constexpr int OFF_T2  = WPC * WBYTES;                 // 149504
constexpr int OFF_TP  = OFF_T2 + Kdim * 32 * 4;       // +8192 = 157696
constexpr int OFF_LPI = OFF_TP + Kdim * Kdim * 4;     // +16384 = 174080
constexpr int OFF_LS  = OFF_LPI + 256;                // 174336
constexpr int SMEMSZ  = OFF_LS + 256;                 // 174592

__device__ float    gPart[Bseq];       // per-sequence log-likelihoods
__device__ unsigned gDone;             // finished-warp counter (zero-init; finalizer resets)

// ---------------------------------------------------------------------------
// helpers
// ---------------------------------------------------------------------------
__device__ __forceinline__ float ex2f(float x) {
    float r; asm("ex2.approx.ftz.f32 %0, %1;" : "=f"(r) : "f"(x)); return r;
}
__device__ __forceinline__ float lg2f(float x) {
    float r; asm("lg2.approx.ftz.f32 %0, %1;" : "=f"(r) : "f"(x)); return r;
}
__device__ __forceinline__ float warp_sum(float v) {
#pragma unroll
    for (int o = 16; o > 0; o >>= 1) v += __shfl_xor_sync(0xffffffffu, v, o);
    return v;
}
__device__ __forceinline__ double warp_sum_d(double v) {
#pragma unroll
    for (int o = 16; o > 0; o >>= 1) v += __shfl_xor_sync(0xffffffffu, v, o);
    return v;
}
__device__ __forceinline__ void hfma2(unsigned& acc, unsigned a, unsigned b) {
    asm("fma.rn.bf16x2 %0, %1, %2, %0;" : "+r"(acc) : "r"(a), "r"(b));
}
__device__ __forceinline__ unsigned hadd2(unsigned a, unsigned b) {
    unsigned r; asm("add.rn.bf16x2 %0, %1, %2;" : "=r"(r) : "r"(a), "r"(b)); return r;
}
__device__ __forceinline__ unsigned hmul2(unsigned a, unsigned b) {
    unsigned r; asm("mul.rn.bf16x2 %0, %1, %2;" : "=r"(r) : "r"(a), "r"(b)); return r;
}
__device__ __forceinline__ unsigned prmt(unsigned a, unsigned b, unsigned sel) {
    unsigned r; asm("prmt.b32 %0, %1, %2, %3;" : "=r"(r) : "r"(a), "r"(b), "r"(sel)); return r;
}
__device__ __forceinline__ float blo(unsigned u) { return __uint_as_float(u << 16); }
__device__ __forceinline__ float bhi(unsigned u) { return __uint_as_float(u & 0xffff0000u); }
__device__ __forceinline__ unsigned pack_bf16x2(float lo, float hi) {
    unsigned r; asm("cvt.rn.bf16x2.f32 %0, %1, %2;" : "=r"(r) : "f"(hi), "f"(lo)); return r;
}
__device__ __forceinline__ float bf16r(float x) { return blo(pack_bf16x2(x, 0.f)); }
__device__ __forceinline__ void cpasync16(void* dst, const void* src) {
    unsigned d = (unsigned)__cvta_generic_to_shared(dst);
    asm volatile("cp.async.ca.shared.global [%0], [%1], 16;" :: "r"(d), "l"(src));
}
template <int N> __device__ __forceinline__ void wait_group() {
    asm volatile("cp.async.wait_group %0;" :: "n"(N));
}
__device__ __forceinline__ void commit_group() {
    asm volatile("cp.async.commit_group;");
}

// issue one 32-step emission block (64 rows x 32 floats) into staging buffer
__device__ __forceinline__ void issue_stage(float* sbuf, const float* gbase, int l) {
#pragma unroll
    for (int i = 0; i < 16; i++) {
        int m   = (i << 5) + l;
        int row = m >> 3;
        int c4  = (m & 7) << 2;
        cpasync16(sbuf + row * STRIDE + c4, gbase + (size_t)row * Nn + c4);
    }
    commit_group();
}

// ---------------------------------------------------------------------------
// one forward step: smem ping-pong exchange, depth-8 bf16 accumulation,
// all-bf16 epilogue (PRMT cross-half gather + hadd2 + hmul2 by packed f).
// lane l owns states (2l, 2l+1); qw = packed bf16x2(q_{2l}, q_{2l+1}).
// ---------------------------------------------------------------------------
__device__ __forceinline__ void step(const unsigned* qR, unsigned* qW, int l,
                                     const unsigned* Ta, const unsigned* Tb,
                                     unsigned fpk, unsigned& qw) {
    __syncwarp();
    const uint4* qp = (const uint4*)qR;
    unsigned A0 = 0, A1 = 0, A2 = 0, A3 = 0;
    unsigned B0 = 0, B1 = 0, B2 = 0, B3 = 0;
#pragma unroll
    for (int i = 0; i < 8; i++) {
        uint4 w = qp[i];
        hfma2(A0, w.x, Ta[4 * i + 0]);  hfma2(B0, w.x, Tb[4 * i + 0]);
        hfma2(A1, w.y, Ta[4 * i + 1]);  hfma2(B1, w.y, Tb[4 * i + 1]);
        hfma2(A2, w.z, Ta[4 * i + 2]);  hfma2(B2, w.z, Tb[4 * i + 2]);
        hfma2(A3, w.w, Ta[4 * i + 3]);  hfma2(B3, w.w, Tb[4 * i + 3]);
    }
    unsigned a = hadd2(hadd2(A0, A1), hadd2(A2, A3));   // (aLo, aHi) state A
    unsigned b = hadd2(hadd2(B0, B1), hadd2(B2, B3));   // (bLo, bHi) state B
    unsigned hi = prmt(a, b, 0x7632u);   // (a.hi, b.hi)
    unsigned lo = prmt(a, b, 0x5410u);   // (a.lo, b.lo)
    unsigned d2 = hadd2(hi, lo);         // (dA, dB)
    qw = hmul2(d2, fpk);                 // q' = f * d
    qW[l] = qw;
}

// ---------------------------------------------------------------------------
// fully fused kernel: inline prep + forward scan + final reduction
// 128 CTAs x 8 warps; one sequence per warp
// ---------------------------------------------------------------------------
__global__ void __launch_bounds__(WPC * 32, 1) fwd_kernel(const float* __restrict__ lp,
                                                          const float* __restrict__ pi,
                                                          const float* __restrict__ T,
                                                          float* __restrict__ out) {
    extern __shared__ char dsm[];
    const int tid = threadIdx.x;
    const int wid = tid >> 5;
    const int l   = tid & 31;
    const int b   = blockIdx.x * WPC + wid;
    const float* base = lp + (size_t)b * NSs;

    float*    st0  = (float*)(dsm + wid * WBYTES);
    float*    st1  = st0 + Kdim * STRIDE;
    unsigned* q0   = (unsigned*)(dsm + wid * WBYTES + STBYTES);
    unsigned* q1   = q0 + 32;
    unsigned* sT2  = (unsigned*)(dsm + OFF_T2);
    float*    sTp  = (float*)(dsm + OFF_TP);
    float*    sLpi = (float*)(dsm + OFF_LPI);
    float*    sLs  = (float*)(dsm + OFF_LS);

    // stage first two emission blocks FIRST — DRAM latency hides under prep
    issue_stage(st0, base, l);
    issue_stage(st1, base + TBLK, l);

    // ---- inline prep: softmax rows of T (8 warps x 8 rows) ----
#pragma unroll 1
    for (int r = wid; r < Kdim; r += WPC) {
        float a = T[r * Kdim + l], c = T[r * Kdim + l + 32];
        float m = fmaxf(a, c);
#pragma unroll
        for (int o = 16; o > 0; o >>= 1) m = fmaxf(m, __shfl_xor_sync(0xffffffffu, m, o));
        float ea = expf(a - m), ec = expf(c - m);
        float s = warp_sum(ea + ec);
        float inv = 1.0f / s;
        sTp[r * Kdim + l]      = ea * inv;
        sTp[r * Kdim + l + 32] = ec * inv;
    }
    __syncthreads();
    // pack T columns as bf16x2 row-pairs
    for (int idx = tid; idx < Kdim * 32; idx += WPC * 32) {
        int k = idx >> 5, j = idx & 31;
        sT2[idx] = pack_bf16x2(sTp[(2 * j) * Kdim + k], sTp[(2 * j + 1) * Kdim + k]);
    }
    if (wid == 1) {  // log_softmax(pi) * log2e
        float pa = pi[l], pb = pi[l + 32];
        float m2 = fmaxf(pa, pb);
#pragma unroll
        for (int o = 16; o > 0; o >>= 1) m2 = fmaxf(m2, __shfl_xor_sync(0xffffffffu, m2, o));
        float sp = warp_sum(expf(pa - m2) + expf(pb - m2));
        float ls = logf(sp);
        sLpi[l]      = (pa - m2 - ls) * L2E;
        sLpi[l + 32] = (pb - m2 - ls) * L2E;
    }
    if (wid == 0) {  // stationary distribution (6 power iters) + bf16(T) bias
        float wA = 1.0f / 64.0f, wB = 1.0f / 64.0f;
#pragma unroll 1
        for (int it = 0; it < 6; it++) {
            float nA = 0.f, nB = 0.f;
#pragma unroll 4
            for (int j = 0; j < 32; j++) {
                float wj0 = __shfl_sync(0xffffffffu, wA, j);
                float wj1 = __shfl_sync(0xffffffffu, wB, j);
                nA = fmaf(wj0, sTp[(2 * j) * Kdim + 2 * l],     nA);
                nA = fmaf(wj1, sTp[(2 * j + 1) * Kdim + 2 * l], nA);
                nB = fmaf(wj0, sTp[(2 * j) * Kdim + 2 * l + 1],     nB);
                nB = fmaf(wj1, sTp[(2 * j + 1) * Kdim + 2 * l + 1], nB);
            }
            float S = warp_sum(nA + nB);
            wA = nA / S; wB = nB / S;
        }
        float nA = 0.f, nB = 0.f, dA = 0.f, dB = 0.f;
#pragma unroll 4
        for (int j = 0; j < 32; j++) {
            float wj0 = __shfl_sync(0xffffffffu, wA, j);
            float wj1 = __shfl_sync(0xffffffffu, wB, j);
            float t00 = sTp[(2 * j) * Kdim + 2 * l];
            float t10 = sTp[(2 * j + 1) * Kdim + 2 * l];
            float t01 = sTp[(2 * j) * Kdim + 2 * l + 1];
            float t11 = sTp[(2 * j + 1) * Kdim + 2 * l + 1];
            nA += wj0 * t00 + wj1 * t10;
            nB += wj0 * t01 + wj1 * t11;
            dA += wj0 * bf16r(t00) + wj1 * bf16r(t10);
            dB += wj0 * bf16r(t01) + wj1 * bf16r(t11);
        }
        sLs[2 * l]     = log2f(nA / dA);
        sLs[2 * l + 1] = log2f(nB / dB);
    }
    __syncthreads();

    // ---- per-warp T columns into registers (from smem) ----
    unsigned Ta[32], Tb[32];
    {
        const uint4* pa = (const uint4*)(sT2 + (2 * l) * 32);
        const uint4* pb = (const uint4*)(sT2 + (2 * l + 1) * 32);
#pragma unroll
        for (int i = 0; i < 8; i++) { ((uint4*)Ta)[i] = pa[i]; ((uint4*)Tb)[i] = pb[i]; }
    }
    const float lpiA = sLpi[2 * l], lpiB = sLpi[2 * l + 1];
    const float lsA  = sLs[2 * l],  lsB  = sLs[2 * l + 1];

    wait_group<1>();
    __syncwarp();

    // t = 0: q = exp2(lp0*log2e + log2_pi); then t = 1..3 (live q ends in q1)
    float4 e4A = *(const float4*)(st0 + (2 * l) * STRIDE);
    float4 e4B = *(const float4*)(st0 + (2 * l + 1) * STRIDE);
    unsigned qw = pack_bf16x2(ex2f(fmaf(e4A.x, L2E, lpiA)),
                              ex2f(fmaf(e4B.x, L2E, lpiB)));
    q0[l] = qw;
    {
        unsigned f1 = pack_bf16x2(ex2f(fmaf(e4A.y, L2E, lsA)), ex2f(fmaf(e4B.y, L2E, lsB)));
        unsigned f2 = pack_bf16x2(ex2f(fmaf(e4A.z, L2E, lsA)), ex2f(fmaf(e4B.z, L2E, lsB)));
        unsigned f3 = pack_bf16x2(ex2f(fmaf(e4A.w, L2E, lsA)), ex2f(fmaf(e4B.w, L2E, lsB)));
        step(q0, q1, l, Ta, Tb, f1, qw);
        step(q1, q0, l, Ta, Tb, f2, qw);
        step(q0, q1, l, Ta, Tb, f3, qw);
    }

    double cacc = 0.0;
    float  gp   = 0.0f;

#pragma unroll 1
    for (int t0 = 4; t0 < NSs; t0 += 4) {
        if ((t0 & (TBLK - 1)) == 0) {
            int k = t0 >> 5;
            float* refill = ((k + 1) & 1) ? st1 : st0;
            if (t0 + TBLK < NSs)
                issue_stage(refill, base + t0 + TBLK, l);
            float S = warp_sum(blo(qw) + bhi(qw));        // renorm every 32 steps
            float g = lg2f(S);
            cacc += (double)g;
            gp = -g;
            if (t0 + TBLK < NSs) wait_group<1>(); else wait_group<0>();
            __syncwarp();
        }
        const float* sb = ((t0 >> 5) & 1) ? st1 : st0;
        const int tt = t0 & (TBLK - 1);
        float4 eA = *(const float4*)(sb + (2 * l) * STRIDE + tt);
        float4 eB = *(const float4*)(sb + (2 * l + 1) * STRIDE + tt);

        // off-chain f-factor precompute + pack (bias correction + pending renorm)
        unsigned f0 = pack_bf16x2(ex2f(fmaf(eA.x, L2E, lsA + gp)),
                                  ex2f(fmaf(eB.x, L2E, lsB + gp)));
        unsigned f1 = pack_bf16x2(ex2f(fmaf(eA.y, L2E, lsA)), ex2f(fmaf(eB.y, L2E, lsB)));
        unsigned f2 = pack_bf16x2(ex2f(fmaf(eA.z, L2E, lsA)), ex2f(fmaf(eB.z, L2E, lsB)));
        unsigned f3 = pack_bf16x2(ex2f(fmaf(eA.w, L2E, lsA)), ex2f(fmaf(eB.w, L2E, lsB)));
        gp = 0.0f;

        // groups always start with live q in q1 (4 swaps return it to q1)
        step(q1, q0, l, Ta, Tb, f0, qw);
        step(q0, q1, l, Ta, Tb, f1, qw);
        step(q1, q0, l, Ta, Tb, f2, qw);
        step(q0, q1, l, Ta, Tb, f3, qw);
    }

    float S = warp_sum(blo(qw) + bhi(qw));
    if (l == 0) gPart[b] = LN2 * (float)(cacc + (double)lg2f(S));

    // ---- fused deterministic final reduction (last warp to finish) ----
    __threadfence();
    unsigned rank = 0;
    if (l == 0) rank = atomicAdd(&gDone, 1u);
    rank = __shfl_sync(0xffffffffu, rank, 0);
    if (rank == Bseq - 1) {
        __threadfence();
        double v = 0.0;
        for (int i = l; i < Bseq; i += 32) v += (double)gPart[i];  // fixed order
        v = warp_sum_d(v);                                          // fixed tree
        if (l == 0) {
            out[0] = (float)v;
            gDone = 0u;   // reset for next graph replay
        }
    }
}

// ---------------------------------------------------------------------------
extern "C" void kernel_launch(void* const* d_in, const int* in_sizes, int n_in,
                              void* d_out, int out_size) {
    const float* lp = (const float*)d_in[0];  // log_pdf (K, N)
    const float* pi = (const float*)d_in[1];  // pi (K,)
    const float* T  = (const float*)d_in[2];  // T (K, K)
    (void)in_sizes; (void)n_in; (void)out_size;

    cudaFuncSetAttribute(fwd_kernel, cudaFuncAttributeMaxDynamicSharedMemorySize, SMEMSZ);
    fwd_kernel<<<CTAS, WPC * 32, SMEMSZ>>>(lp, pi, T, (float*)d_out);
}

// round 16
// speedup vs baseline: 1.1517x; 1.0180x over previous
#include <cuda_runtime.h>
#include <cstddef>

// Fixed problem shape: K=64, N=1048576, NS=1024, B=1024
constexpr int   Kdim  = 64;
constexpr long  Nn    = 1048576;
constexpr int   NSs   = 1024;
constexpr int   Bseq  = 1024;
constexpr int   SPC   = 8;            // sequences per CTA (= MMA rows used)
constexpr int   CTAS  = Bseq / SPC;   // 128
constexpr int   TBLK  = 32;           // staging block (time steps) == renorm period
constexpr int   NBLK  = NSs / TBLK;   // 32
constexpr float L2E   = 1.4426950408889634f;
constexpr float LN2   = 0.6931471805599453f;

// staging layout: per seq, 2 blocks of [64 states][36 words] (+4 pad words)
constexpr int ROWW   = 36;                       // words per state-row (144B, 16B aligned)
constexpr int BLKW   = Kdim * ROWW;              // 2304 words per block
constexpr int SEQW   = 2 * BLKW + 4;             // 4612 words (odd-ish stride: 4-way LDS max)
// smem offsets (bytes)
constexpr int OFF_ST  = 0;
constexpr int OFF_SA  = SPC * SEQW * 4;          // 147584
constexpr int SA_BUF  = 8 * 144;                 // 1152 B per A buffer (8 rows x 144B)
constexpr int OFF_TP  = OFF_SA + 2 * SA_BUF;     // 149888
constexpr int OFF_LPI = OFF_TP + Kdim * Kdim * 4;// 166272
constexpr int OFF_LS  = OFF_LPI + 256;           // 166528
constexpr int OFF_RED = OFF_LS + 256;            // 166784
constexpr int OFF_GP  = OFF_RED + 256;           // 167040
constexpr int SMEMSZ  = OFF_GP + 64;             // 167104

__device__ float    gPart[Bseq];
__device__ unsigned gDone;    // zero-init; finalizer resets (graph-replay safe)

// ---------------------------------------------------------------------------
// helpers
// ---------------------------------------------------------------------------
__device__ __forceinline__ float ex2f(float x) {
    float r; asm("ex2.approx.ftz.f32 %0, %1;" : "=f"(r) : "f"(x)); return r;
}
__device__ __forceinline__ float lg2f(float x) {
    float r; asm("lg2.approx.ftz.f32 %0, %1;" : "=f"(r) : "f"(x)); return r;
}
__device__ __forceinline__ float warp_sum(float v) {
#pragma unroll
    for (int o = 16; o > 0; o >>= 1) v += __shfl_xor_sync(0xffffffffu, v, o);
    return v;
}
__device__ __forceinline__ double warp_sum_d(double v) {
#pragma unroll
    for (int o = 16; o > 0; o >>= 1) v += __shfl_xor_sync(0xffffffffu, v, o);
    return v;
}
__device__ __forceinline__ unsigned pack_bf16x2(float lo, float hi) {
    unsigned r; asm("cvt.rn.bf16x2.f32 %0, %1, %2;" : "=r"(r) : "f"(hi), "f"(lo)); return r;
}
__device__ __forceinline__ float blo(unsigned u) { return __uint_as_float(u << 16); }
__device__ __forceinline__ float bf16r(float x) { return blo(pack_bf16x2(x, 0.f)); }
__device__ __forceinline__ void cpasync16(void* dst, const void* src) {
    unsigned d = (unsigned)__cvta_generic_to_shared(dst);
    asm volatile("cp.async.ca.shared.global [%0], [%1], 16;" :: "r"(d), "l"(src));
}
template <int N> __device__ __forceinline__ void wait_group() {
    asm volatile("cp.async.wait_group %0;" :: "n"(N));
}
__device__ __forceinline__ void commit_group() {
    asm volatile("cp.async.commit_group;");
}
__device__ __forceinline__ void sts32(unsigned addr, unsigned v) {
    asm volatile("st.shared.b32 [%0], %1;" :: "r"(addr), "r"(v));
}
__device__ __forceinline__ void ldmx4(unsigned& r0, unsigned& r1, unsigned& r2,
                                      unsigned& r3, unsigned addr) {
    asm volatile("ldmatrix.sync.aligned.m8n8.x4.shared.b16 {%0,%1,%2,%3}, [%4];"
                 : "=r"(r0), "=r"(r1), "=r"(r2), "=r"(r3) : "r"(addr));
}
// D(16x8,f32) += A(16x16,bf16) x B(16x8,bf16); rows 8-15 of A forced zero (a1=a3=0)
__device__ __forceinline__ void mma8(float& d0, float& d1, float& d2, float& d3,
                                     unsigned aLo, unsigned aHi,
                                     unsigned b0, unsigned b1) {
    asm volatile(
        "mma.sync.aligned.m16n8k16.row.col.f32.bf16.bf16.f32 "
        "{%0,%1,%2,%3}, {%4,%5,%6,%7}, {%8,%9}, {%0,%1,%2,%3};"
        : "+f"(d0), "+f"(d1), "+f"(d2), "+f"(d3)
        : "r"(aLo), "r"(0u), "r"(aHi), "r"(0u), "r"(b0), "r"(b1));
}

// stage one 32-step block (64 rows x 32 floats) of one sequence into [state][time]
__device__ __forceinline__ void issue_stage(float* sbuf, const float* gbase, int l) {
#pragma unroll
    for (int i = 0; i < 16; i++) {
        int m   = (i << 5) + l;
        int row = m >> 3;
        int c4  = (m & 7) << 2;
        cpasync16(sbuf + row * ROWW + c4, gbase + (size_t)row * Nn + c4);
    }
    commit_group();
}

// ---------------------------------------------------------------------------
// fused kernel: inline prep + tensor-core forward scan + final reduction
// 128 CTAs x 8 warps; CTA owns 8 sequences (MMA rows); warp owns 8 states (n-tile)
// ---------------------------------------------------------------------------
__global__ void __launch_bounds__(256, 1) fwd_kernel(const float* __restrict__ lp,
                                                     const float* __restrict__ pi,
                                                     const float* __restrict__ T,
                                                     float* __restrict__ out) {
    extern __shared__ char dsm[];
    float*    stf  = (float*)(dsm + OFF_ST);
    float*    sTp  = (float*)(dsm + OFF_TP);
    float*    sLpi = (float*)(dsm + OFF_LPI);
    float*    sLs  = (float*)(dsm + OFF_LS);
    float*    red  = (float*)(dsm + OFF_RED);
    float*    gps  = (float*)(dsm + OFF_GP);

    const int tid = threadIdx.x;
    const int wid = tid >> 5;
    const int l   = tid & 31;
    const int s   = l >> 2;                // seq (D-frag row), 0..7
    const int c   = l & 3;                 // D-frag col group
    const int n0  = 8 * wid + 2 * c;       // lane's states n0, n0+1 (D cols)
    const int nB  = 8 * wid + s;           // B-frag column
    const int bb  = blockIdx.x * SPC;      // first global seq of this CTA

    // warp wid stages seq wid; first two blocks issued before prep (hides DRAM)
    const float* gseq = lp + (size_t)(bb + wid) * NSs;
    float* stW = stf + wid * SEQW;
    issue_stage(stW, gseq, l);
    issue_stage(stW + BLKW, gseq + TBLK, l);

    // ---- inline prep: softmax rows of T (8 warps x 8 rows) ----
#pragma unroll 1
    for (int r = wid; r < Kdim; r += 8) {
        float a = T[r * Kdim + l], cc = T[r * Kdim + l + 32];
        float m = fmaxf(a, cc);
#pragma unroll
        for (int o = 16; o > 0; o >>= 1) m = fmaxf(m, __shfl_xor_sync(0xffffffffu, m, o));
        float ea = expf(a - m), ec = expf(cc - m);
        float ss = warp_sum(ea + ec);
        float inv = 1.0f / ss;
        sTp[r * Kdim + l]      = ea * inv;
        sTp[r * Kdim + l + 32] = ec * inv;
    }
    __syncthreads();
    if (wid == 1) {  // log_softmax(pi) * log2e
        float pa = pi[l], pb = pi[l + 32];
        float m2 = fmaxf(pa, pb);
#pragma unroll
        for (int o = 16; o > 0; o >>= 1) m2 = fmaxf(m2, __shfl_xor_sync(0xffffffffu, m2, o));
        float sp = warp_sum(expf(pa - m2) + expf(pb - m2));
        float ls = logf(sp);
        sLpi[l]      = (pa - m2 - ls) * L2E;
        sLpi[l + 32] = (pb - m2 - ls) * L2E;
    }
    if (wid == 0) {  // stationary distribution (6 iters) + bf16(T) bias correction
        float wA = 1.0f / 64.0f, wB = 1.0f / 64.0f;
#pragma unroll 1
        for (int it = 0; it < 6; it++) {
            float nA = 0.f, nBv = 0.f;
#pragma unroll 4
            for (int j = 0; j < 32; j++) {
                float wj0 = __shfl_sync(0xffffffffu, wA, j);
                float wj1 = __shfl_sync(0xffffffffu, wB, j);
                nA  = fmaf(wj0, sTp[(2 * j) * Kdim + 2 * l],     nA);
                nA  = fmaf(wj1, sTp[(2 * j + 1) * Kdim + 2 * l], nA);
                nBv = fmaf(wj0, sTp[(2 * j) * Kdim + 2 * l + 1],     nBv);
                nBv = fmaf(wj1, sTp[(2 * j + 1) * Kdim + 2 * l + 1], nBv);
            }
            float S = warp_sum(nA + nBv);
            wA = nA / S; wB = nBv / S;
        }
        float nA = 0.f, nBv = 0.f, dA = 0.f, dB = 0.f;
#pragma unroll 4
        for (int j = 0; j < 32; j++) {
            float wj0 = __shfl_sync(0xffffffffu, wA, j);
            float wj1 = __shfl_sync(0xffffffffu, wB, j);
            float t00 = sTp[(2 * j) * Kdim + 2 * l];
            float t10 = sTp[(2 * j + 1) * Kdim + 2 * l];
            float t01 = sTp[(2 * j) * Kdim + 2 * l + 1];
            float t11 = sTp[(2 * j + 1) * Kdim + 2 * l + 1];
            nA  += wj0 * t00 + wj1 * t10;
            nBv += wj0 * t01 + wj1 * t11;
            dA  += wj0 * bf16r(t00) + wj1 * bf16r(t10);
            dB  += wj0 * bf16r(t01) + wj1 * bf16r(t11);
        }
        sLs[2 * l]     = log2f(nA / dA);
        sLs[2 * l + 1] = log2f(nBv / dB);
    }
    __syncthreads();

    // ---- B fragments: T resident in registers forever ----
    // b0 = {T[kb+2c][n], T[kb+2c+1][n]}, b1 = {T[kb+2c+8][n], T[kb+2c+9][n]}, n = nB
    unsigned Bf[8];
#pragma unroll
    for (int kc = 0; kc < 4; kc++) {
        int kb = kc * 16;
        Bf[2 * kc]     = pack_bf16x2(sTp[(kb + 2 * c) * Kdim + nB],
                                     sTp[(kb + 2 * c + 1) * Kdim + nB]);
        Bf[2 * kc + 1] = pack_bf16x2(sTp[(kb + 2 * c + 8) * Kdim + nB],
                                     sTp[(kb + 2 * c + 9) * Kdim + nB]);
    }
    const float ls0  = sLs[n0],  ls1  = sLs[n0 + 1];
    const float lpi0 = sLpi[n0], lpi1 = sLpi[n0 + 1];

    // addresses
    const unsigned saAddr  = (unsigned)__cvta_generic_to_shared(dsm + OFF_SA);
    const unsigned lmBase  = saAddr + (l & 7) * 144 + (l >> 3) * 16;  // ldmatrix lane addr
    const unsigned stsBase = saAddr + s * 144 + n0 * 2;               // q store addr
    const int      eb      = s * SEQW + n0 * ROWW;                    // emission base (words)

    wait_group<1>();
    __syncthreads();

    // t = 0: q = exp2(lp0*log2e + log2_pi), write A buffer 0
    float q0, q1;
    {
        float e0 = stf[eb], e1 = stf[eb + ROWW];
        q0 = ex2f(fmaf(e0, L2E, lpi0));
        q1 = ex2f(fmaf(e1, L2E, lpi1));
        sts32(stsBase, pack_bf16x2(q0, q1));
    }

    double cacc = 0.0;
    float  gp   = 0.0f;

#pragma unroll 1
    for (int t = 1; t < NSs; t++) {
        if ((t & (TBLK - 1)) == 0) {
            __syncthreads();                       // drain reads of block k-1
            int k = t >> 5;
            if (k < NBLK - 1)
                issue_stage(stW + ((k + 1) & 1) * BLKW, gseq + (size_t)(k + 1) * TBLK, l);
            // renorm partials (every 32 steps): warp's 8 states per seq
            float part = q0 + q1;
            part += __shfl_xor_sync(0xffffffffu, part, 1);
            part += __shfl_xor_sync(0xffffffffu, part, 2);
            if (c == 0) red[wid * 8 + s] = part;
            if (k < NBLK - 1) wait_group<1>(); else wait_group<0>();
            __syncthreads();
            if (wid == 0 && l < 8) {
                float tot = 0.f;
#pragma unroll
                for (int w2 = 0; w2 < 8; w2++) tot += red[w2 * 8 + l];
                float g = lg2f(tot);
                cacc += (double)g;
                gps[l] = -g;
            }
            __syncthreads();
            gp = gps[s];
        }
        __syncthreads();    // publish A[(t+1)&1] stores from step t-1

        // A fragments: rows 0-7 (seqs), k = 0..63, from previous A buffer
        unsigned lm = lmBase + ((t + 1) & 1) * SA_BUF;
        unsigned a0, a1, a2, a3, b0, b1, b2, b3;
        ldmx4(a0, a1, a2, a3, lm);        // k 0-7, 8-15, 16-23, 24-31
        ldmx4(b0, b1, b2, b3, lm + 64);   // k 32-63

        float D0 = 0.f, D1 = 0.f, D2 = 0.f, D3 = 0.f;
        float E0 = 0.f, E1 = 0.f, E2 = 0.f, E3 = 0.f;
        mma8(D0, D1, D2, D3, a0, a1, Bf[0], Bf[1]);   // k 0-15
        mma8(D0, D1, D2, D3, a2, a3, Bf[2], Bf[3]);   // k 16-31
        mma8(E0, E1, E2, E3, b0, b1, Bf[4], Bf[5]);   // k 32-47
        mma8(E0, E1, E2, E3, b2, b3, Bf[6], Bf[7]);   // k 48-63

        // emissions + f factors (off A-chain)
        int ea = eb + ((t >> 5) & 1) * BLKW + (t & (TBLK - 1));
        float e0 = stf[ea], e1 = stf[ea + ROWW];
        float f0 = ex2f(fmaf(e0, L2E, ls0 + gp));
        float f1 = ex2f(fmaf(e1, L2E, ls1 + gp));
        gp = 0.0f;

        q0 = f0 * (D0 + E0);
        q1 = f1 * (D1 + E1);
        sts32(stsBase + (t & 1) * SA_BUF, pack_bf16x2(q0, q1));
    }

    // ---- final per-seq log-likelihoods ----
    __syncthreads();
    {
        float part = q0 + q1;
        part += __shfl_xor_sync(0xffffffffu, part, 1);
        part += __shfl_xor_sync(0xffffffffu, part, 2);
        if (c == 0) red[wid * 8 + s] = part;
    }
    __syncthreads();
    if (wid == 0 && l < 8) {
        float tot = 0.f;
#pragma unroll
        for (int w2 = 0; w2 < 8; w2++) tot += red[w2 * 8 + l];
        gPart[bb + l] = LN2 * (float)(cacc + (double)lg2f(tot));
    }

    // ---- fused deterministic final reduction (last CTA) ----
    __threadfence();
    if (wid == 0) {
        unsigned rank = 0;
        if (l == 0) rank = atomicAdd(&gDone, 1u);
        rank = __shfl_sync(0xffffffffu, rank, 0);
        if (rank == CTAS - 1) {
            __threadfence();
            double v = 0.0;
            for (int i = l; i < Bseq; i += 32) v += (double)gPart[i];  // fixed order
            v = warp_sum_d(v);                                          // fixed tree
            if (l == 0) {
                out[0] = (float)v;
                gDone = 0u;   // reset for next graph replay
            }
        }
    }
}

// ---------------------------------------------------------------------------
extern "C" void kernel_launch(void* const* d_in, const int* in_sizes, int n_in,
                              void* d_out, int out_size) {
    const float* lp = (const float*)d_in[0];  // log_pdf (K, N)
    const float* pi = (const float*)d_in[1];  // pi (K,)
    const float* T  = (const float*)d_in[2];  // T (K, K)
    (void)in_sizes; (void)n_in; (void)out_size;

    cudaFuncSetAttribute(fwd_kernel, cudaFuncAttributeMaxDynamicSharedMemorySize, SMEMSZ);
    fwd_kernel<<<CTAS, 256, SMEMSZ>>>(lp, pi, T, (float*)d_out);
}